// round 11
// baseline (speedup 1.0000x reference)
#include <cuda_runtime.h>
#include <cstddef>

// GATNE-T fused, TWO warps per batch element (R11).
// CTA = 64 threads = 2 warps, one b per CTA, grid = B.
// Warp w gathers edge types {2w, 2w+1} (20 loads each), computes scores for
// its own 2 types, then both warps cooperate on softmax/natt and split the
// E=128 projection 64/64. Cross-warp data via smem + cheap 2-warp barriers.
//
// Inputs (metadata order):
//  0 targets   int32  [B]
//  1 types     int32  [B]
//  2 neighbors int32  [B,T,S]
//  3 base_node_embeddings float [V,E]
//  4 node_type_embeddings float [V,T,D]
//  5 trans_weights    float [T,D,E]
//  6 trans_weights_s1 float [T,D,A]
//  7 trans_weights_s2 float [T,A,1]
// Output: float [B,E]

namespace {
constexpr int T = 4;
constexpr int S = 10;
constexpr int D = 32;
constexpr int E = 128;
constexpr int A = 32;
}

__device__ __forceinline__ float tanh_approx(float x) {
    float y;
    asm("tanh.approx.f32 %0, %1;" : "=f"(y) : "f"(x));
    return y;
}

__global__ __launch_bounds__(64) void gatne_2warp(
    const int*   __restrict__ targets,
    const int*   __restrict__ types,
    const int*   __restrict__ neighbors,  // [B,T,S]
    const float* __restrict__ base_emb,   // [V,E]
    const float* __restrict__ nte,        // [V,T,D]
    const float* __restrict__ tw,         // [T,D,E]
    const float* __restrict__ tw1,        // [T,D,A]
    const float* __restrict__ tw2,        // [T,A]
    float*       __restrict__ out)        // [B,E]
{
    const int w    = threadIdx.x >> 5;    // 0 or 1
    const int lane = threadIdx.x & 31;

    __shared__ float sh_agg[T][D];
    __shared__ float sh_nat[D];
    __shared__ float sh_sc[T];
    __shared__ float sh_red[2];

    const int b   = blockIdx.x;
    const int ty  = types[b];      // broadcast LDG
    const int tgt = targets[b];    // broadcast LDG

    // PREFETCH the random base_emb gather (this warp's half: 64 floats).
    const float2 bv = __ldg((const float2*)(base_emb + (size_t)tgt * E
                                            + 64 * w) + lane);

    // ---- neighbor indices for this warp's 2 edge types (20 ints) ----
    const int* nbp = neighbors + (size_t)b * (T * S) + 20 * w;
    int nb = 0;
    if (lane < 20) nb = nbp[lane];

    // ---- gather + mean: 20 independent coalesced 128B loads ----
    const int t0 = 2 * w, t1 = 2 * w + 1;
    float acc0 = 0.0f, acc1 = 0.0f;
    #pragma unroll
    for (int k = 0; k < S; ++k) {
        const int v0 = __shfl_sync(0xffffffffu, nb, k);
        const int v1 = __shfl_sync(0xffffffffu, nb, k + S);
        acc0 += __ldg(&nte[(size_t)v0 * (T * D) + t0 * D + lane]);
        acc1 += __ldg(&nte[(size_t)v1 * (T * D) + t1 * D + lane]);
    }
    acc0 *= (1.0f / (float)S);
    acc1 *= (1.0f / (float)S);
    sh_agg[t0][lane] = acc0;
    sh_agg[t1][lane] = acc1;
    __syncthreads();                                   // B1

    // ---- scores for this warp's 2 types (lane = a) ----
    // W1 read straight from L1 (16KB table, resident); each loaded value is
    // used for BOTH t-chains.
    {
        const float* w1 = tw1 + (size_t)ty * (D * A) + lane;
        const float tw2v = __ldg(&tw2[ty * A + lane]);
        float d0a = 0.f, d0b = 0.f, d1a = 0.f, d1b = 0.f;
        const float4* ap0 = (const float4*)sh_agg[t0];
        const float4* ap1 = (const float4*)sh_agg[t1];
        #pragma unroll
        for (int q = 0; q < D / 4; ++q) {
            const float4 v0 = ap0[q];                  // LDS.128 broadcast
            const float4 v1 = ap1[q];
            const float wa = __ldg(w1 + (4 * q + 0) * A);
            const float wb = __ldg(w1 + (4 * q + 1) * A);
            const float wc = __ldg(w1 + (4 * q + 2) * A);
            const float wd = __ldg(w1 + (4 * q + 3) * A);
            d0a = fmaf(v0.x, wa, d0a); d0b = fmaf(v0.y, wb, d0b);
            d0a = fmaf(v0.z, wc, d0a); d0b = fmaf(v0.w, wd, d0b);
            d1a = fmaf(v1.x, wa, d1a); d1b = fmaf(v1.y, wb, d1b);
            d1a = fmaf(v1.z, wc, d1a); d1b = fmaf(v1.w, wd, d1b);
        }
        float u0 = tanh_approx(d0a + d0b) * tw2v;
        float u1 = tanh_approx(d1a + d1b) * tw2v;
        #pragma unroll
        for (int off = 16; off > 0; off >>= 1) {
            u0 += __shfl_xor_sync(0xffffffffu, u0, off);
            u1 += __shfl_xor_sync(0xffffffffu, u1, off);
        }
        if (lane == 0) { sh_sc[t0] = u0; sh_sc[t1] = u1; }
    }
    __syncthreads();                                   // B2

    // ---- softmax over T=4 + attended embedding (warp 0 writes natt) ----
    {
        const float s0 = sh_sc[0], s1 = sh_sc[1], s2 = sh_sc[2], s3 = sh_sc[3];
        const float m  = fmaxf(fmaxf(s0, s1), fmaxf(s2, s3));
        const float e0 = __expf(s0 - m), e1 = __expf(s1 - m);
        const float e2 = __expf(s2 - m), e3 = __expf(s3 - m);
        const float inv = 1.0f / (e0 + e1 + e2 + e3);
        if (w == 0) {
            sh_nat[lane] = (e0 * sh_agg[0][lane] + e1 * sh_agg[1][lane] +
                            e2 * sh_agg[2][lane] + e3 * sh_agg[3][lane]) * inv;
        }
    }
    __syncthreads();                                   // B3

    // ---- projection: warp w covers e in [64w, 64w+64); lane owns float2 ----
    const float* wbase = tw + (size_t)ty * (D * E) + 64 * w + 2 * lane;
    float2 pa = make_float2(0.f, 0.f);
    float2 pb = make_float2(0.f, 0.f);
    const float4* np = (const float4*)sh_nat;
    #pragma unroll
    for (int q = 0; q < D / 4; ++q) {
        const float4 n4 = np[q];                       // LDS.128 broadcast
        const float2 w0 = __ldg((const float2*)(wbase + (4 * q + 0) * E));
        const float2 w1 = __ldg((const float2*)(wbase + (4 * q + 1) * E));
        const float2 w2 = __ldg((const float2*)(wbase + (4 * q + 2) * E));
        const float2 w3 = __ldg((const float2*)(wbase + (4 * q + 3) * E));
        pa.x = fmaf(n4.x, w0.x, pa.x); pa.y = fmaf(n4.x, w0.y, pa.y);
        pb.x = fmaf(n4.y, w1.x, pb.x); pb.y = fmaf(n4.y, w1.y, pb.y);
        pa.x = fmaf(n4.z, w2.x, pa.x); pa.y = fmaf(n4.z, w2.y, pa.y);
        pb.x = fmaf(n4.w, w3.x, pb.x); pb.y = fmaf(n4.w, w3.y, pb.y);
    }
    const float2 val = make_float2(pa.x + pb.x + bv.x, pa.y + pb.y + bv.y);

    // ---- l2 norm: per-warp butterfly (64 values) + cross-warp combine ----
    float ss = val.x * val.x + val.y * val.y;
    #pragma unroll
    for (int off = 16; off > 0; off >>= 1)
        ss += __shfl_xor_sync(0xffffffffu, ss, off);
    if (lane == 0) sh_red[w] = ss;
    __syncthreads();                                   // B4
    const float r = rsqrtf(fmaxf(sh_red[0] + sh_red[1], 1e-12f));

    ((float2*)(out + (size_t)b * E + 64 * w))[lane] =
        make_float2(val.x * r, val.y * r);
}

extern "C" void kernel_launch(void* const* d_in, const int* in_sizes, int n_in,
                              void* d_out, int out_size) {
    const int*   targets   = (const int*)  d_in[0];
    const int*   types     = (const int*)  d_in[1];
    const int*   neighbors = (const int*)  d_in[2];
    const float* base_emb  = (const float*)d_in[3];
    const float* nte       = (const float*)d_in[4];
    const float* tw        = (const float*)d_in[5];
    const float* tw1       = (const float*)d_in[6];
    const float* tw2       = (const float*)d_in[7];
    float* out = (float*)d_out;

    const int B = in_sizes[0];
    gatne_2warp<<<B, 64>>>(targets, types, neighbors,
                           base_emb, nte, tw, tw1, tw2, out);
}

// round 12
// speedup vs baseline: 1.2239x; 1.2239x over previous
#include <cuda_runtime.h>
#include <cuda_fp16.h>
#include <cstddef>

// GATNE-T fused (R12): R9 warp-per-b skeleton + fp16 weight copies to halve
// L1 wavefront traffic on the projection / attention weight reads.
//
// Inputs (metadata order):
//  0 targets   int32  [B]
//  1 types     int32  [B]
//  2 neighbors int32  [B,T,S]
//  3 base_node_embeddings float [V,E]
//  4 node_type_embeddings float [V,T,D]
//  5 trans_weights    float [T,D,E]
//  6 trans_weights_s1 float [T,D,A]
//  7 trans_weights_s2 float [T,A,1]
// Output: float [B,E]

namespace {
constexpr int T = 4;
constexpr int S = 10;
constexpr int D = 32;
constexpr int E = 128;
constexpr int A = 32;
constexpr int NW = 8;          // warps per CTA
}

// fp16 weight copies (rebuilt every launch; deterministic).
__device__ __half  g_twh[T * D * E];            // [t][d][e]  (32KB)
__device__ __half2 g_tw1h2[T * (D / 2) * A];    // [t][dp][a] = (w1[2dp][a], w1[2dp+1][a])

__device__ __forceinline__ float tanh_approx(float x) {
    float y;
    asm("tanh.approx.f32 %0, %1;" : "=f"(y) : "f"(x));
    return y;
}

// ---------------------------------------------------------------------------
// K0: build fp16 weight tables (tiny: 16K + 2K elements).
// ---------------------------------------------------------------------------
__global__ void k_convert(const float* __restrict__ tw,
                          const float* __restrict__ tw1)
{
    const int i = blockIdx.x * blockDim.x + threadIdx.x;
    if (i < T * D * E) g_twh[i] = __float2half_rn(tw[i]);
    if (i < T * (D / 2) * A) {
        const int t  = i / ((D / 2) * A);
        const int r  = i % ((D / 2) * A);
        const int dp = r / A;
        const int a  = r % A;
        const float* p = tw1 + (size_t)t * (D * A);
        g_tw1h2[i] = __floats2half2_rn(p[(2 * dp) * A + a],
                                       p[(2 * dp + 1) * A + a]);
    }
}

// ---------------------------------------------------------------------------
// Main fused kernel: warp-per-b (R9 structure).
// ---------------------------------------------------------------------------
__global__ __launch_bounds__(32 * NW) void gatne_warp(
    const int*   __restrict__ targets,
    const int*   __restrict__ types,
    const int*   __restrict__ neighbors,  // [B,T,S]
    const float* __restrict__ base_emb,   // [V,E]
    const float* __restrict__ nte,        // [V,T,D]
    const float* __restrict__ tw2,        // [T,A]
    float*       __restrict__ out,        // [B,E]
    int B)
{
    const int wid  = threadIdx.x >> 5;
    const int lane = threadIdx.x & 31;

    __shared__ float sh_agg[NW][T][D];
    __shared__ float sh_nat[NW][D];

    const int b = blockIdx.x * NW + wid;
    if (b >= B) return;

    const int ty  = types[b];      // broadcast LDG
    const int tgt = targets[b];    // broadcast LDG

    // PREFETCH the random base_emb gather (overlaps neighbor gathers).
    const float4 bv = __ldg((const float4*)(base_emb + (size_t)tgt * E) + lane);

    // neighbor indices: 2 coalesced loads for 40 ints
    const int* nbp = neighbors + (size_t)b * (T * S);
    const int nbv0 = nbp[lane];
    const int nbv1 = (lane < T * S - 32) ? nbp[32 + lane] : 0;

    // gather + mean: 40 independent coalesced 128B loads, lane = d
    float acc[T];
    #pragma unroll
    for (int t = 0; t < T; ++t) acc[t] = 0.0f;

    #pragma unroll
    for (int t = 0; t < T; ++t) {
        #pragma unroll
        for (int s = 0; s < S; ++s) {
            const int flat = t * S + s;
            const int v = (flat < 32)
                ? __shfl_sync(0xffffffffu, nbv0, flat)
                : __shfl_sync(0xffffffffu, nbv1, flat - 32);
            acc[t] += __ldg(&nte[(size_t)v * (T * D) + t * D + lane]);
        }
    }

    // attention weights: fp16 packed, 16 coalesced 128B wavefronts
    float w1col[D];                        // W1[ty][d][lane], lane = a
    {
        const __half2* w1h = g_tw1h2 + (size_t)ty * ((D / 2) * A);
        #pragma unroll
        for (int dp = 0; dp < D / 2; ++dp) {
            const float2 f = __half22float2(w1h[dp * A + lane]);
            w1col[2 * dp]     = f.x;
            w1col[2 * dp + 1] = f.y;
        }
    }
    const float tw2v = __ldg(&tw2[ty * A + lane]);

    #pragma unroll
    for (int t = 0; t < T; ++t) {
        acc[t] *= (1.0f / (float)S);       // agg[t][lane]
        sh_agg[wid][t][lane] = acc[t];
    }
    __syncwarp();

    // scores: u[t][a] = tanh(agg[t] . W1[:,a]);  sc[t] = sum_a u*w2
    float score[T];
    #pragma unroll
    for (int t = 0; t < T; ++t) {
        float d0 = 0.0f, d1 = 0.0f;
        const float4* ap = (const float4*)sh_agg[wid][t];
        #pragma unroll
        for (int q = 0; q < D / 4; ++q) {
            const float4 v4 = ap[q];       // broadcast LDS.128
            d0 = fmaf(v4.x, w1col[4 * q + 0], d0);
            d1 = fmaf(v4.y, w1col[4 * q + 1], d1);
            d0 = fmaf(v4.z, w1col[4 * q + 2], d0);
            d1 = fmaf(v4.w, w1col[4 * q + 3], d1);
        }
        float u = tanh_approx(d0 + d1) * tw2v;
        #pragma unroll
        for (int off = 16; off > 0; off >>= 1)
            u += __shfl_xor_sync(0xffffffffu, u, off);
        score[t] = u;
    }

    // softmax over T=4 + attended embedding (lane = d)
    const float m  = fmaxf(fmaxf(score[0], score[1]),
                           fmaxf(score[2], score[3]));
    const float e0 = __expf(score[0] - m), e1 = __expf(score[1] - m);
    const float e2 = __expf(score[2] - m), e3 = __expf(score[3] - m);
    const float inv = 1.0f / (e0 + e1 + e2 + e3);
    sh_nat[wid][lane] = (e0 * acc[0] + e1 * acc[1] +
                         e2 * acc[2] + e3 * acc[3]) * inv;
    __syncwarp();

    // projection: lane owns e in [4*lane, 4*lane+4); fp16 weights ->
    // 2 wavefronts per d instead of 4 (64 wf/b total). fp32 accumulate.
    const __half* wb = g_twh + (size_t)ty * (D * E) + 4 * lane;
    float4 a4 = make_float4(0.f, 0.f, 0.f, 0.f);
    float4 b4 = make_float4(0.f, 0.f, 0.f, 0.f);
    const float4* np = (const float4*)sh_nat[wid];
    #pragma unroll
    for (int q = 0; q < D / 4; ++q) {
        const float4 n4 = np[q];           // broadcast LDS.128
        #pragma unroll
        for (int j = 0; j < 4; ++j) {
            const int d = 4 * q + j;
            const float nd = (j == 0) ? n4.x : (j == 1) ? n4.y
                           : (j == 2) ? n4.z : n4.w;
            const uint2 raw = __ldg((const uint2*)(wb + d * E)); // 4 halves
            const float2 f0 = __half22float2(*(const __half2*)&raw.x);
            const float2 f1 = __half22float2(*(const __half2*)&raw.y);
            if (j & 1) {
                b4.x = fmaf(nd, f0.x, b4.x); b4.y = fmaf(nd, f0.y, b4.y);
                b4.z = fmaf(nd, f1.x, b4.z); b4.w = fmaf(nd, f1.y, b4.w);
            } else {
                a4.x = fmaf(nd, f0.x, a4.x); a4.y = fmaf(nd, f0.y, a4.y);
                a4.z = fmaf(nd, f1.x, a4.z); a4.w = fmaf(nd, f1.y, a4.w);
            }
        }
    }

    const float4 val = make_float4(a4.x + b4.x + bv.x, a4.y + b4.y + bv.y,
                                   a4.z + b4.z + bv.z, a4.w + b4.w + bv.w);

    // l2 norm: warp butterfly = exact sum over all 128 outputs
    float ss = val.x * val.x + val.y * val.y + val.z * val.z + val.w * val.w;
    #pragma unroll
    for (int off = 16; off > 0; off >>= 1)
        ss += __shfl_xor_sync(0xffffffffu, ss, off);
    const float r = rsqrtf(fmaxf(ss, 1e-12f));

    const float4 o = make_float4(val.x * r, val.y * r, val.z * r, val.w * r);
    ((float4*)(out + (size_t)b * E))[lane] = o;
}

extern "C" void kernel_launch(void* const* d_in, const int* in_sizes, int n_in,
                              void* d_out, int out_size) {
    const int*   targets   = (const int*)  d_in[0];
    const int*   types     = (const int*)  d_in[1];
    const int*   neighbors = (const int*)  d_in[2];
    const float* base_emb  = (const float*)d_in[3];
    const float* nte       = (const float*)d_in[4];
    const float* tw        = (const float*)d_in[5];
    const float* tw1       = (const float*)d_in[6];
    const float* tw2       = (const float*)d_in[7];
    float* out = (float*)d_out;

    const int B = in_sizes[0];

    k_convert<<<(T * D * E + 255) / 256, 256>>>(tw, tw1);

    const int grid = (B + NW - 1) / NW;
    gatne_warp<<<grid, 32 * NW>>>(targets, types, neighbors,
                                  base_emb, nte, tw2, out, B);
}